// round 2
// baseline (speedup 1.0000x reference)
#include <cuda_runtime.h>
#include <math.h>

#define BATCH   4096
#define IN_DIM  1024
#define OUT_DIM 1024
#define DPC     16
#define N_DEND  16384

#define BM 128
#define BN 128
#define BK 8
#define TM 8
#define TN 8
#define NTHREADS 256

typedef unsigned long long ull;

// ---- packed f32x2 helpers (ptxas never emits FFMA2 from C++; PTX only) ----
__device__ __forceinline__ ull pk2(float lo, float hi) {
    ull r;
    asm("mov.b64 %0, {%1, %2};" : "=l"(r) : "f"(lo), "f"(hi));
    return r;
}
__device__ __forceinline__ void upk2(ull v, float& lo, float& hi) {
    asm("mov.b64 {%0, %1}, %2;" : "=f"(lo), "=f"(hi) : "l"(v));
}
__device__ __forceinline__ void ffma2(ull& acc, ull a, ull b) {
    asm("fma.rn.f32x2 %0, %1, %2, %0;" : "+l"(acc) : "l"(a), "l"(b));
}

// ---- boost precompute: boost[d] = exp((1/DPC - duty[d]) * BOOST_STRENGTH) ----
__device__ float g_boost[N_DEND];

__global__ void boost_kernel(const float* __restrict__ duty) {
    int i = blockIdx.x * blockDim.x + threadIdx.x;
    if (i < N_DEND) g_boost[i] = expf((1.0f / DPC - duty[i]) * 2.0f);
}

// ---- fused GEMM (dend = x @ w1^T + b1) + boosted WTA + grouped output ----
__global__ __launch_bounds__(NTHREADS)
void dendrite_kernel(const float* __restrict__ x,
                     const float* __restrict__ w1,
                     const float* __restrict__ b1,
                     const float* __restrict__ w2,
                     const float* __restrict__ b2,
                     float* __restrict__ out) {
    __shared__ float As[2][BK][BM];
    __shared__ float Ws[2][BK][BN];

    const int tid   = threadIdx.x;
    const int tx    = tid & 15;     // 0..15 along N
    const int ty    = tid >> 4;     // 0..15 along M
    const int ntile = blockIdx.x;
    const int btile = blockIdx.y;

    // global tile-load mapping: each thread loads one float4 of A and one of W
    const int lrow = tid >> 1;        // 0..127
    const int lcol = (tid & 1) * 4;   // 0 or 4

    const float* Ag = x  + (size_t)(btile * BM + lrow) * IN_DIM + lcol;
    const float* Wg = w1 + (size_t)(ntile * BN + lrow) * IN_DIM + lcol;

    ull acc2[TM][TN / 2];
#pragma unroll
    for (int i = 0; i < TM; ++i)
#pragma unroll
        for (int j = 0; j < TN / 2; ++j) acc2[i][j] = 0ull;

    // preload tile 0
    {
        float4 av = *(const float4*)(Ag);
        float4 wv = *(const float4*)(Wg);
        As[0][lcol + 0][lrow] = av.x;
        As[0][lcol + 1][lrow] = av.y;
        As[0][lcol + 2][lrow] = av.z;
        As[0][lcol + 3][lrow] = av.w;
        Ws[0][lcol + 0][lrow] = wv.x;
        Ws[0][lcol + 1][lrow] = wv.y;
        Ws[0][lcol + 2][lrow] = wv.z;
        Ws[0][lcol + 3][lrow] = wv.w;
    }
    __syncthreads();

    int cur = 0;
    const int NT = IN_DIM / BK;  // 128 k-steps
    for (int t = 0; t < NT; ++t) {
        float4 av2, wv2;
        const bool more = (t + 1 < NT);
        if (more) {
            av2 = *(const float4*)(Ag + (size_t)(t + 1) * BK);
            wv2 = *(const float4*)(Wg + (size_t)(t + 1) * BK);
        }

#pragma unroll
        for (int kk = 0; kk < BK; ++kk) {
            float4 a0 = *(const float4*)&As[cur][kk][ty * TM];
            float4 a1 = *(const float4*)&As[cur][kk][ty * TM + 4];
            float4 w0 = *(const float4*)&Ws[cur][kk][tx * TN];
            float4 w4 = *(const float4*)&Ws[cur][kk][tx * TN + 4];
            ull n0 = pk2(w0.x, w0.y);
            ull n1 = pk2(w0.z, w0.w);
            ull n2 = pk2(w4.x, w4.y);
            ull n3 = pk2(w4.z, w4.w);
            float am[8] = {a0.x, a0.y, a0.z, a0.w, a1.x, a1.y, a1.z, a1.w};
#pragma unroll
            for (int i = 0; i < TM; ++i) {
                ull ad = pk2(am[i], am[i]);
                ffma2(acc2[i][0], ad, n0);
                ffma2(acc2[i][1], ad, n1);
                ffma2(acc2[i][2], ad, n2);
                ffma2(acc2[i][3], ad, n3);
            }
        }

        if (more) {
            int nxt = cur ^ 1;
            As[nxt][lcol + 0][lrow] = av2.x;
            As[nxt][lcol + 1][lrow] = av2.y;
            As[nxt][lcol + 2][lrow] = av2.z;
            As[nxt][lcol + 3][lrow] = av2.w;
            Ws[nxt][lcol + 0][lrow] = wv2.x;
            Ws[nxt][lcol + 1][lrow] = wv2.y;
            Ws[nxt][lcol + 2][lrow] = wv2.z;
            Ws[nxt][lcol + 3][lrow] = wv2.w;
            __syncthreads();
            cur = nxt;
        }
    }

    // ---- epilogue: per cell (16 dendrites = 2 adjacent threads), boosted argmax ----
    float acc[TM][TN];
#pragma unroll
    for (int i = 0; i < TM; ++i)
#pragma unroll
        for (int j2 = 0; j2 < TN / 2; ++j2)
            upk2(acc2[i][j2], acc[i][2 * j2], acc[i][2 * j2 + 1]);

    const int c0 = ntile * BN + tx * TN;  // first dendrite col of this thread
    float bst[TN], bv1[TN];
#pragma unroll
    for (int j = 0; j < TN; ++j) {
        bst[j] = g_boost[c0 + j];
        bv1[j] = b1[c0 + j];
    }

    const int o = ntile * (BN / DPC) + (tx >> 1);  // global output cell
    const float* w2p = w2 + (size_t)o * DPC;
    const float b2v = b2[o];
    const bool lowhalf = ((tx & 1) == 0);  // owns dendrites 0..7 of the cell

#pragma unroll
    for (int i = 0; i < TM; ++i) {
        float bmax = -INFINITY;
        int ja = 0;
        float dja = 0.0f;
#pragma unroll
        for (int j = 0; j < TN; ++j) {
            float d = acc[i][j] + bv1[j];
            float bb = d * bst[j];
            if (bb > bmax) { bmax = bb; ja = j; dja = d; }  // strict > keeps first idx
        }
        float obmax = __shfl_xor_sync(0xffffffffu, bmax, 1);
        float odja  = __shfl_xor_sync(0xffffffffu, dja, 1);
        int   oja   = __shfl_xor_sync(0xffffffffu, ja, 1);
        if (lowhalf) {
            // jnp.argmax tie-break: lowest index wins -> low half wins on >=
            bool sw  = (bmax >= obmax);
            float dv = sw ? dja : odja;
            int   dw = sw ? ja : (DPC / 2 + oja);
            int brow = btile * BM + ty * TM + i;
            out[(size_t)brow * OUT_DIM + o] = dv * w2p[dw] + b2v;
        }
    }
}

extern "C" void kernel_launch(void* const* d_in, const int* in_sizes, int n_in,
                              void* d_out, int out_size) {
    const float* x    = (const float*)d_in[0];
    const float* w1   = (const float*)d_in[1];
    const float* b1   = (const float*)d_in[2];
    const float* duty = (const float*)d_in[3];
    const float* w2   = (const float*)d_in[4];
    const float* b2   = (const float*)d_in[5];
    float* out = (float*)d_out;

    boost_kernel<<<N_DEND / 256, 256>>>(duty);
    dim3 grid(N_DEND / BN, BATCH / BM);
    dendrite_kernel<<<grid, NTHREADS>>>(x, w1, b1, w2, b2, out);
}

// round 3
// speedup vs baseline: 1.0001x; 1.0001x over previous
#include <cuda_runtime.h>
#include <math.h>

#define BATCH   4096
#define IN_DIM  1024
#define OUT_DIM 1024
#define DPC     16
#define N_DEND  16384

#define BM 128
#define BN 128
#define BK 8
#define TM 8
#define TN 8
#define NTHREADS 256

typedef unsigned long long ull;

// ---- packed f32x2 helpers (ptxas never emits FFMA2 from C++; PTX only) ----
__device__ __forceinline__ ull pk2(float lo, float hi) {
    ull r;
    asm("mov.b64 %0, {%1, %2};" : "=l"(r) : "f"(lo), "f"(hi));
    return r;
}
__device__ __forceinline__ void upk2(ull v, float& lo, float& hi) {
    asm("mov.b64 {%0, %1}, %2;" : "=f"(lo), "=f"(hi) : "l"(v));
}
__device__ __forceinline__ void ffma2(ull& acc, ull a, ull b) {
    asm("fma.rn.f32x2 %0, %1, %2, %0;" : "+l"(acc) : "l"(a), "l"(b));
}

// ---- boost precompute: boost[d] = exp((1/DPC - duty[d]) * BOOST_STRENGTH) ----
__device__ float g_boost[N_DEND];

__global__ void boost_kernel(const float* __restrict__ duty) {
    int i = blockIdx.x * blockDim.x + threadIdx.x;
    if (i < N_DEND) g_boost[i] = expf((1.0f / DPC - duty[i]) * 2.0f);
}

// ---- fused GEMM (dend = x @ w1^T + b1) + boosted WTA + grouped output ----
__global__ __launch_bounds__(NTHREADS)
void dendrite_kernel(const float* __restrict__ x,
                     const float* __restrict__ w1,
                     const float* __restrict__ b1,
                     const float* __restrict__ w2,
                     const float* __restrict__ b2,
                     float* __restrict__ out) {
    __shared__ float As[2][BK][BM];
    __shared__ float Ws[2][BK][BN];

    const int tid   = threadIdx.x;
    const int tx    = tid & 15;     // 0..15 along N
    const int ty    = tid >> 4;     // 0..15 along M
    const int ntile = blockIdx.x;
    const int btile = blockIdx.y;

    // global tile-load mapping: each thread loads one float4 of A and one of W
    const int lrow = tid >> 1;        // 0..127
    const int lcol = (tid & 1) * 4;   // 0 or 4

    const float* Ag = x  + (size_t)(btile * BM + lrow) * IN_DIM + lcol;
    const float* Wg = w1 + (size_t)(ntile * BN + lrow) * IN_DIM + lcol;

    ull acc2[TM][TN / 2];
#pragma unroll
    for (int i = 0; i < TM; ++i)
#pragma unroll
        for (int j = 0; j < TN / 2; ++j) acc2[i][j] = 0ull;

    // preload tile 0
    {
        float4 av = *(const float4*)(Ag);
        float4 wv = *(const float4*)(Wg);
        As[0][lcol + 0][lrow] = av.x;
        As[0][lcol + 1][lrow] = av.y;
        As[0][lcol + 2][lrow] = av.z;
        As[0][lcol + 3][lrow] = av.w;
        Ws[0][lcol + 0][lrow] = wv.x;
        Ws[0][lcol + 1][lrow] = wv.y;
        Ws[0][lcol + 2][lrow] = wv.z;
        Ws[0][lcol + 3][lrow] = wv.w;
    }
    __syncthreads();

    int cur = 0;
    const int NT = IN_DIM / BK;  // 128 k-steps
    for (int t = 0; t < NT; ++t) {
        float4 av2, wv2;
        const bool more = (t + 1 < NT);
        if (more) {
            av2 = *(const float4*)(Ag + (size_t)(t + 1) * BK);
            wv2 = *(const float4*)(Wg + (size_t)(t + 1) * BK);
        }

#pragma unroll
        for (int kk = 0; kk < BK; ++kk) {
            float4 a0 = *(const float4*)&As[cur][kk][ty * TM];
            float4 a1 = *(const float4*)&As[cur][kk][ty * TM + 4];
            float4 w0 = *(const float4*)&Ws[cur][kk][tx * TN];
            float4 w4 = *(const float4*)&Ws[cur][kk][tx * TN + 4];
            ull n0 = pk2(w0.x, w0.y);
            ull n1 = pk2(w0.z, w0.w);
            ull n2 = pk2(w4.x, w4.y);
            ull n3 = pk2(w4.z, w4.w);
            float am[8] = {a0.x, a0.y, a0.z, a0.w, a1.x, a1.y, a1.z, a1.w};
#pragma unroll
            for (int i = 0; i < TM; ++i) {
                ull ad = pk2(am[i], am[i]);
                ffma2(acc2[i][0], ad, n0);
                ffma2(acc2[i][1], ad, n1);
                ffma2(acc2[i][2], ad, n2);
                ffma2(acc2[i][3], ad, n3);
            }
        }

        if (more) {
            int nxt = cur ^ 1;
            As[nxt][lcol + 0][lrow] = av2.x;
            As[nxt][lcol + 1][lrow] = av2.y;
            As[nxt][lcol + 2][lrow] = av2.z;
            As[nxt][lcol + 3][lrow] = av2.w;
            Ws[nxt][lcol + 0][lrow] = wv2.x;
            Ws[nxt][lcol + 1][lrow] = wv2.y;
            Ws[nxt][lcol + 2][lrow] = wv2.z;
            Ws[nxt][lcol + 3][lrow] = wv2.w;
            __syncthreads();
            cur = nxt;
        }
    }

    // ---- epilogue: per cell (16 dendrites = 2 adjacent threads), boosted argmax ----
    float acc[TM][TN];
#pragma unroll
    for (int i = 0; i < TM; ++i)
#pragma unroll
        for (int j2 = 0; j2 < TN / 2; ++j2)
            upk2(acc2[i][j2], acc[i][2 * j2], acc[i][2 * j2 + 1]);

    const int c0 = ntile * BN + tx * TN;  // first dendrite col of this thread
    float bst[TN], bv1[TN];
#pragma unroll
    for (int j = 0; j < TN; ++j) {
        bst[j] = g_boost[c0 + j];
        bv1[j] = b1[c0 + j];
    }

    const int o = ntile * (BN / DPC) + (tx >> 1);  // global output cell
    const float* w2p = w2 + (size_t)o * DPC;
    const float b2v = b2[o];
    const bool lowhalf = ((tx & 1) == 0);  // owns dendrites 0..7 of the cell

#pragma unroll
    for (int i = 0; i < TM; ++i) {
        float bmax = -INFINITY;
        int ja = 0;
        float dja = 0.0f;
#pragma unroll
        for (int j = 0; j < TN; ++j) {
            float d = acc[i][j] + bv1[j];
            float bb = d * bst[j];
            if (bb > bmax) { bmax = bb; ja = j; dja = d; }  // strict > keeps first idx
        }
        float obmax = __shfl_xor_sync(0xffffffffu, bmax, 1);
        float odja  = __shfl_xor_sync(0xffffffffu, dja, 1);
        int   oja   = __shfl_xor_sync(0xffffffffu, ja, 1);
        if (lowhalf) {
            // jnp.argmax tie-break: lowest index wins -> low half wins on >=
            bool sw  = (bmax >= obmax);
            float dv = sw ? dja : odja;
            int   dw = sw ? ja : (DPC / 2 + oja);
            int brow = btile * BM + ty * TM + i;
            out[(size_t)brow * OUT_DIM + o] = dv * w2p[dw] + b2v;
        }
    }
}

extern "C" void kernel_launch(void* const* d_in, const int* in_sizes, int n_in,
                              void* d_out, int out_size) {
    const float* x    = (const float*)d_in[0];
    const float* w1   = (const float*)d_in[1];
    const float* b1   = (const float*)d_in[2];
    const float* duty = (const float*)d_in[3];
    const float* w2   = (const float*)d_in[4];
    const float* b2   = (const float*)d_in[5];
    float* out = (float*)d_out;

    boost_kernel<<<N_DEND / 256, 256>>>(duty);
    dim3 grid(N_DEND / BN, BATCH / BM);
    dendrite_kernel<<<grid, NTHREADS>>>(x, w1, b1, w2, b2, out);
}

// round 6
// speedup vs baseline: 2.1195x; 2.1192x over previous
#include <cuda_runtime.h>
#include <cuda_fp16.h>
#include <math.h>
#include <stdint.h>

#define BATCH   4096
#define IN_DIM  1024
#define OUT_DIM 1024
#define DPC     16
#define N_DEND  16384

#define TILE_M  256
#define TILE_N  128
#define BK      64            // fp16 k per stage chunk (128B rows)
#define NCHUNK  48            // 3 passes * 1024 / 64
#define THREADS 512
#define STAGES  4
#define STAGE_SZ 49152        // A 32KB + B 16KB
#define B_OFF    32768
#define EPI_PITCH 132
#define SMEM_BYTES (STAGES * STAGE_SZ)   // 196608; epilogue overlays
#define WSCALE  1024.0f
#define TAU     0.05f
#define FLAG_CAP 65536

// ---------------- static device scratch ----------------
__device__ __align__(256) __half g_xh[BATCH * IN_DIM];
__device__ __align__(256) __half g_xl[BATCH * IN_DIM];
__device__ __align__(256) __half g_wh[(size_t)N_DEND * IN_DIM];
__device__ __align__(256) __half g_wl[(size_t)N_DEND * IN_DIM];
__device__ float g_boost[N_DEND];
__device__ float g_b1s[N_DEND];
__device__ int   g_flags[FLAG_CAP];
__device__ int   g_nflag;

// ---------------- PTX helpers (portable to compute_103) ----------------
__device__ __forceinline__ uint32_t smem_u32(const void* p) {
    uint32_t a;
    asm("{ .reg .u64 t; cvta.to.shared.u64 t, %1; cvt.u32.u64 %0, t; }" : "=r"(a) : "l"(p));
    return a;
}
__device__ __forceinline__ void cp16(uint32_t dst, const void* src) {
    asm volatile("cp.async.cg.shared.global [%0], [%1], 16;" :: "r"(dst), "l"(src) : "memory");
}
#define CP_COMMIT() asm volatile("cp.async.commit_group;" ::: "memory")

#define LDSM4(r, addr) \
    asm volatile("ldmatrix.sync.aligned.m8n8.x4.shared.b16 {%0,%1,%2,%3}, [%4];" \
                 : "=r"((r)[0]), "=r"((r)[1]), "=r"((r)[2]), "=r"((r)[3]) : "r"(addr))

__device__ __forceinline__ void mma16816(float* c, const uint32_t* a,
                                         uint32_t b0, uint32_t b1) {
    asm volatile(
        "mma.sync.aligned.m16n8k16.row.col.f32.f16.f16.f32 "
        "{%0,%1,%2,%3}, {%4,%5,%6,%7}, {%8,%9}, {%0,%1,%2,%3};"
        : "+f"(c[0]), "+f"(c[1]), "+f"(c[2]), "+f"(c[3])
        : "r"(a[0]), "r"(a[1]), "r"(a[2]), "r"(a[3]), "r"(b0), "r"(b1));
}

// ---------------- prep kernels ----------------
__global__ void prep_misc_kernel(const float* __restrict__ duty, const float* __restrict__ b1) {
    int i = blockIdx.x * blockDim.x + threadIdx.x;
    if (i < N_DEND) {
        g_boost[i] = expf((1.0f / DPC - duty[i]) * 2.0f);
        g_b1s[i]   = b1[i] * WSCALE;
    }
    if (i == 0) g_nflag = 0;
}
__global__ void split_x_kernel(const float* __restrict__ x) {
    int i = blockIdx.x * blockDim.x + threadIdx.x;
    if (i < BATCH * IN_DIM) {
        float v = x[i];
        __half h = __float2half_rn(v);
        g_xh[i] = h;
        g_xl[i] = __float2half_rn(v - __half2float(h));
    }
}
__global__ void split_w_kernel(const float* __restrict__ w1) {
    size_t i = (size_t)blockIdx.x * blockDim.x + threadIdx.x;
    if (i < (size_t)N_DEND * IN_DIM) {
        float v = w1[i] * WSCALE;
        __half h = __float2half_rn(v);
        g_wh[i] = h;
        g_wl[i] = __float2half_rn(v - __half2float(h));
    }
}

// ---------------- stage loader ----------------
__device__ __forceinline__ void load_chunk(int t, int tid, uint32_t sb, int m0, int n0) {
    const int pass = t >> 4;                  // 0: xh*wh, 1: xh*wl, 2: xl*wh
    const int kc   = (t & 15) * BK;
    const __half* Ab = (pass == 2) ? g_xl : g_xh;
    const __half* Bb = (pass == 1) ? g_wl : g_wh;
    const uint32_t sA = sb + (uint32_t)(t & (STAGES - 1)) * STAGE_SZ;
    const uint32_t sB = sA + B_OFF;
#pragma unroll
    for (int i = 0; i < 4; ++i) {             // A: 256 rows x 8 chunks
        int e = tid + i * THREADS;
        int r = e >> 3, c = e & 7;
        cp16(sA + r * 128 + ((c ^ (r & 7)) << 4),
             Ab + (size_t)(m0 + r) * IN_DIM + kc + c * 8);
    }
#pragma unroll
    for (int i = 0; i < 2; ++i) {             // B: 128 rows x 8 chunks
        int e = tid + i * THREADS;
        int r = e >> 3, c = e & 7;
        cp16(sB + r * 128 + ((c ^ (r & 7)) << 4),
             Bb + (size_t)(n0 + r) * IN_DIM + kc + c * 8);
    }
    CP_COMMIT();
}

// ---------------- main fused GEMM + WTA epilogue ----------------
__global__ __launch_bounds__(THREADS, 1)
void gemm_kernel(const float* __restrict__ w2, const float* __restrict__ b2,
                 float* __restrict__ out) {
    extern __shared__ char smem[];
    const uint32_t sb = smem_u32(smem);
    const int tid  = threadIdx.x;
    const int wid  = tid >> 5, lane = tid & 31;
    const int wm   = wid & 3;              // warp m index (64-row block)
    const int wn   = wid >> 2;             // warp n index (32-col block)
    const int ntile = blockIdx.x, btile = blockIdx.y;
    const int m0 = btile * TILE_M, n0 = ntile * TILE_N;

    const int h      = lane >> 4;                      // k-half selector
    const int aRow   = wm * 64 + (lane & 15);
    const int bRow   = wn * 32 + (lane & 15);
    const uint32_t aOff = (uint32_t)aRow * 128;
    const uint32_t bOff = (uint32_t)bRow * 128;
    uint32_t swzA[4], swzB[4];
#pragma unroll
    for (int ks = 0; ks < 4; ++ks) {
        swzA[ks] = (uint32_t)(((ks * 2 + h) ^ (aRow & 7)) << 4);
        swzB[ks] = (uint32_t)(((ks * 2 + h) ^ (bRow & 7)) << 4);
    }

    float c[4][4][4];
#pragma unroll
    for (int i = 0; i < 4; ++i)
#pragma unroll
        for (int j = 0; j < 4; ++j)
#pragma unroll
            for (int k = 0; k < 4; ++k) c[i][j][k] = 0.0f;

    load_chunk(0, tid, sb, m0, n0);
    load_chunk(1, tid, sb, m0, n0);
    load_chunk(2, tid, sb, m0, n0);

#pragma unroll 1
    for (int t = 0; t < NCHUNK; ++t) {
        if (t <= NCHUNK - 3)      asm volatile("cp.async.wait_group 2;" ::: "memory");
        else if (t == NCHUNK - 2) asm volatile("cp.async.wait_group 1;" ::: "memory");
        else                      asm volatile("cp.async.wait_group 0;" ::: "memory");
        __syncthreads();

        if (t + 3 < NCHUNK) load_chunk(t + 3, tid, sb, m0, n0);

        const uint32_t sA = sb + (uint32_t)(t & (STAGES - 1)) * STAGE_SZ;
        const uint32_t sB = sA + B_OFF;
#pragma unroll
        for (int ks = 0; ks < 4; ++ks) {
            uint32_t a[4][4], b[2][4];
#pragma unroll
            for (int mt = 0; mt < 4; ++mt)
                LDSM4(a[mt], sA + aOff + (uint32_t)mt * 2048 + swzA[ks]);
#pragma unroll
            for (int nh = 0; nh < 2; ++nh)
                LDSM4(b[nh], sB + bOff + (uint32_t)nh * 2048 + swzB[ks]);
#pragma unroll
            for (int mt = 0; mt < 4; ++mt) {
#pragma unroll
                for (int nt = 0; nt < 4; ++nt)
                    mma16816(c[mt][nt], a[mt],
                             b[nt >> 1][nt & 1], b[nt >> 1][(nt & 1) + 2]);
            }
        }
    }
    __syncthreads();

    // ---- dump accumulators to smem (overlay pipeline stages) ----
    float* Df = (float*)smem;
    {
        const int g = lane >> 2, q = lane & 3;
#pragma unroll
        for (int mt = 0; mt < 4; ++mt) {
            const int r0 = wm * 64 + mt * 16 + g;
#pragma unroll
            for (int nt = 0; nt < 4; ++nt) {
                const int col = wn * 32 + nt * 8 + q * 2;
                *(float2*)&Df[(size_t)r0 * EPI_PITCH + col] =
                    make_float2(c[mt][nt][0], c[mt][nt][1]);
                *(float2*)&Df[(size_t)(r0 + 8) * EPI_PITCH + col] =
                    make_float2(c[mt][nt][2], c[mt][nt][3]);
            }
        }
    }
    __syncthreads();

    // ---- boosted winner-take-all + output ----
#pragma unroll
    for (int i = 0; i < 4; ++i) {
        const int p    = tid + i * THREADS;      // 0..2047
        const int row  = p >> 3;                 // 0..255
        const int cell = p & 7;                  // 0..7
        const float* dp = &Df[(size_t)row * EPI_PITCH + cell * 16];
        const int d0 = n0 + cell * 16;           // first dendrite of this cell
        float bmax = -INFINITY, bsec = -INFINITY, dja = 0.0f;
        int ja = 0;
#pragma unroll
        for (int j = 0; j < DPC; ++j) {
            float d  = dp[j] + g_b1s[d0 + j];
            float bb = d * g_boost[d0 + j];
            if (bb > bmax) { bsec = bmax; bmax = bb; ja = j; dja = d; }
            else if (bb > bsec) { bsec = bb; }
        }
        const int o = (n0 >> 4) + cell;
        const int m = m0 + row;
        out[(size_t)m * OUT_DIM + o] =
            (dja * (1.0f / WSCALE)) * w2[o * DPC + ja] + b2[o];
        if (bmax - bsec < TAU) {
            int idx = atomicAdd(&g_nflag, 1);
            if (idx < FLAG_CAP) g_flags[idx] = (m << 10) | o;
        }
    }
}

// ---------------- bit-exact fixup for near-tie cells ----------------
// Reference dend is an ascending-k fp32 FMA chain (round-1 matched it with
// rel_err == 0.0). Reproduce it exactly: one lane per dendrite, sequential
// fmaf over k, then + b1, * boost, 16-wide first-index argmax, fmaf output.
__global__ void fixup_kernel(const float* __restrict__ x,  const float* __restrict__ w1,
                             const float* __restrict__ b1, const float* __restrict__ w2,
                             const float* __restrict__ b2, float* __restrict__ out) {
    int n = g_nflag;
    if (n > FLAG_CAP) n = FLAG_CAP;
    const int gtid = blockIdx.x * blockDim.x + threadIdx.x;
    const int grp  = gtid >> 4;              // one 16-lane group per flagged cell
    const int j    = gtid & 15;              // dendrite within cell
    const int ngrp = (gridDim.x * blockDim.x) >> 4;
    for (int i = grp; i < n; i += ngrp) {
        const int f = g_flags[i];
        const int m = f >> 10, o = f & (OUT_DIM - 1);
        const float* xr = x  + (size_t)m * IN_DIM;
        const float* wr = w1 + (size_t)(o * DPC + j) * IN_DIM;
        float s = 0.0f;
#pragma unroll 8
        for (int k = 0; k < IN_DIM; ++k) s = fmaf(xr[k], wr[k], s);  // order preserved
        float d  = s + b1[o * DPC + j];
        float bb = d * g_boost[o * DPC + j];
        // first-index argmax across the 16-lane group (xor <= 8 stays in-group)
        float bbb = bb, bd = d;
        int   bj  = j;
#pragma unroll
        for (int off = 8; off; off >>= 1) {
            float obb = __shfl_xor_sync(0xffffffffu, bbb, off);
            float od  = __shfl_xor_sync(0xffffffffu, bd,  off);
            int   oj  = __shfl_xor_sync(0xffffffffu, bj,  off);
            if (obb > bbb || (obb == bbb && oj < bj)) { bbb = obb; bd = od; bj = oj; }
        }
        if (j == 0) out[(size_t)m * OUT_DIM + o] = fmaf(bd, w2[o * DPC + bj], b2[o]);
    }
}

extern "C" void kernel_launch(void* const* d_in, const int* in_sizes, int n_in,
                              void* d_out, int out_size) {
    const float* x    = (const float*)d_in[0];
    const float* w1   = (const float*)d_in[1];
    const float* b1   = (const float*)d_in[2];
    const float* duty = (const float*)d_in[3];
    const float* w2   = (const float*)d_in[4];
    const float* b2   = (const float*)d_in[5];
    float* out = (float*)d_out;

    cudaFuncSetAttribute(gemm_kernel, cudaFuncAttributeMaxDynamicSharedMemorySize,
                         SMEM_BYTES);

    prep_misc_kernel<<<N_DEND / 256, 256>>>(duty, b1);
    split_x_kernel<<<(BATCH * IN_DIM) / 256, 256>>>(x);
    split_w_kernel<<<N_DEND * (IN_DIM / 256), 256>>>(w1);

    dim3 grid(N_DEND / TILE_N, BATCH / TILE_M);
    gemm_kernel<<<grid, THREADS, SMEM_BYTES>>>(w2, b2, out);
    fixup_kernel<<<256, 256>>>(x, w1, b1, w2, b2, out);
}

// round 7
// speedup vs baseline: 2.1652x; 1.0216x over previous
#include <cuda_runtime.h>
#include <cuda_fp16.h>
#include <math.h>
#include <stdint.h>

#define BATCH   4096
#define IN_DIM  1024
#define OUT_DIM 1024
#define DPC     16
#define N_DEND  16384

#define TILE_M  256
#define TILE_N  128
#define BK      64            // fp16 k per stage chunk (128B rows)
#define NCHUNK  48            // 3 passes * 1024 / 64
#define THREADS 256
#define STAGES  4
#define STAGE_SZ 49152        // A 32KB + B 16KB
#define B_OFF    32768
#define OFF_META (STAGES * STAGE_SZ)      // 196608
#define SMEM_BYTES (OFF_META + 2048)      // 198656
#define WSCALE  1024.0f
#define TAU     0.01f
#define FLAG_CAP 65536

// ---------------- static device scratch ----------------
__device__ __align__(256) __half g_xh[BATCH * IN_DIM];
__device__ __align__(256) __half g_xl[BATCH * IN_DIM];
__device__ __align__(256) __half g_wh[(size_t)N_DEND * IN_DIM];
__device__ __align__(256) __half g_wl[(size_t)N_DEND * IN_DIM];
__device__ float g_boost[N_DEND];
__device__ float g_b1s[N_DEND];
__device__ int   g_flags[FLAG_CAP];
__device__ int   g_nflag;

// ---------------- PTX helpers (portable to compute_103) ----------------
__device__ __forceinline__ uint32_t smem_u32(const void* p) {
    uint32_t a;
    asm("{ .reg .u64 t; cvta.to.shared.u64 t, %1; cvt.u32.u64 %0, t; }" : "=r"(a) : "l"(p));
    return a;
}
__device__ __forceinline__ void cp16(uint32_t dst, const void* src) {
    asm volatile("cp.async.cg.shared.global [%0], [%1], 16;" :: "r"(dst), "l"(src) : "memory");
}
#define CP_COMMIT() asm volatile("cp.async.commit_group;" ::: "memory")

#define LDSM4(r, addr) \
    asm volatile("ldmatrix.sync.aligned.m8n8.x4.shared.b16 {%0,%1,%2,%3}, [%4];" \
                 : "=r"((r)[0]), "=r"((r)[1]), "=r"((r)[2]), "=r"((r)[3]) : "r"(addr))

__device__ __forceinline__ void mma16816(float* c, const uint32_t* a,
                                         uint32_t b0, uint32_t b1) {
    asm volatile(
        "mma.sync.aligned.m16n8k16.row.col.f32.f16.f16.f32 "
        "{%0,%1,%2,%3}, {%4,%5,%6,%7}, {%8,%9}, {%0,%1,%2,%3};"
        : "+f"(c[0]), "+f"(c[1]), "+f"(c[2]), "+f"(c[3])
        : "r"(a[0]), "r"(a[1]), "r"(a[2]), "r"(a[3]), "r"(b0), "r"(b1));
}

// ---------------- prep kernels ----------------
__global__ void prep_misc_kernel(const float* __restrict__ duty, const float* __restrict__ b1) {
    int i = blockIdx.x * blockDim.x + threadIdx.x;
    if (i < N_DEND) {
        g_boost[i] = expf((1.0f / DPC - duty[i]) * 2.0f);
        g_b1s[i]   = b1[i] * WSCALE;
    }
    if (i == 0) g_nflag = 0;
}
__global__ void split_x_kernel(const float* __restrict__ x) {
    int i = blockIdx.x * blockDim.x + threadIdx.x;
    if (i < BATCH * IN_DIM) {
        float v = x[i];
        __half h = __float2half_rn(v);
        g_xh[i] = h;
        g_xl[i] = __float2half_rn(v - __half2float(h));
    }
}
__global__ void split_w_kernel(const float* __restrict__ w1) {
    size_t i = (size_t)blockIdx.x * blockDim.x + threadIdx.x;
    if (i < (size_t)N_DEND * IN_DIM) {
        float v = w1[i] * WSCALE;
        __half h = __float2half_rn(v);
        g_wh[i] = h;
        g_wl[i] = __float2half_rn(v - __half2float(h));
    }
}

// ---------------- stage loader ----------------
__device__ __forceinline__ void load_chunk(int t, int tid, uint32_t sb, int m0, int n0) {
    const int pass = t >> 4;                  // 0: xh*wh, 1: xh*wl, 2: xl*wh
    const int kc   = (t & 15) * BK;
    const __half* Ab = (pass == 2) ? g_xl : g_xh;
    const __half* Bb = (pass == 1) ? g_wl : g_wh;
    const uint32_t sA = sb + (uint32_t)(t & (STAGES - 1)) * STAGE_SZ;
    const uint32_t sB = sA + B_OFF;
#pragma unroll
    for (int i = 0; i < 8; ++i) {             // A: 256 rows x 8 chunks of 16B
        int e = tid + i * THREADS;
        int r = e >> 3, c = e & 7;
        cp16(sA + r * 128 + ((c ^ (r & 7)) << 4),
             Ab + (size_t)(m0 + r) * IN_DIM + kc + c * 8);
    }
#pragma unroll
    for (int i = 0; i < 4; ++i) {             // B: 128 rows x 8 chunks
        int e = tid + i * THREADS;
        int r = e >> 3, c = e & 7;
        cp16(sB + r * 128 + ((c ^ (r & 7)) << 4),
             Bb + (size_t)(n0 + r) * IN_DIM + kc + c * 8);
    }
    CP_COMMIT();
}

// ---------------- main fused GEMM + WTA epilogue ----------------
__global__ __launch_bounds__(THREADS, 1)
void gemm_kernel(const float* __restrict__ w2, const float* __restrict__ b2,
                 float* __restrict__ out) {
    extern __shared__ char smem[];
    const uint32_t sb = smem_u32(smem);
    const int tid  = threadIdx.x;
    const int wid  = tid >> 5, lane = tid & 31;
    const int wm   = wid & 3;              // warp m index (64-row block)
    const int wn   = wid >> 2;             // warp n index (64-col block)
    const int ntile = blockIdx.x, btile = blockIdx.y;
    const int m0 = btile * TILE_M, n0 = ntile * TILE_N;

    const int h    = lane >> 4;                        // k-half selector
    const int lr   = lane & 15;
    const uint32_t aOff = (uint32_t)(wm * 64 + lr) * 128;
    const uint32_t bOff = (uint32_t)(wn * 64 + lr) * 128 + B_OFF;
    uint32_t swz[4];
#pragma unroll
    for (int ks = 0; ks < 4; ++ks)
        swz[ks] = (uint32_t)(((ks * 2 + h) ^ (lr & 7)) << 4);

    float c[4][8][4];
#pragma unroll
    for (int i = 0; i < 4; ++i)
#pragma unroll
        for (int j = 0; j < 8; ++j)
#pragma unroll
            for (int k = 0; k < 4; ++k) c[i][j][k] = 0.0f;

    load_chunk(0, tid, sb, m0, n0);
    load_chunk(1, tid, sb, m0, n0);
    load_chunk(2, tid, sb, m0, n0);

    float* boost_s = (float*)(smem + OFF_META);
    float* b1s_s   = (float*)(smem + OFF_META + 512);
    float* w2_s    = (float*)(smem + OFF_META + 1024);
    float* b2_s    = (float*)(smem + OFF_META + 1536);
    if (tid < TILE_N) {
        boost_s[tid] = g_boost[n0 + tid];
        b1s_s[tid]   = g_b1s[n0 + tid];
        w2_s[tid]    = w2[n0 + tid];
    }
    if (tid < TILE_N / DPC) b2_s[tid] = b2[(n0 >> 4) + tid];

    uint32_t af[2][16], bf[2][16];

#pragma unroll 1
    for (int t = 0; t < NCHUNK; ++t) {
        if (t <= NCHUNK - 3)      asm volatile("cp.async.wait_group 2;" ::: "memory");
        else if (t == NCHUNK - 2) asm volatile("cp.async.wait_group 1;" ::: "memory");
        else                      asm volatile("cp.async.wait_group 0;" ::: "memory");
        __syncthreads();

        if (t + 3 < NCHUNK) load_chunk(t + 3, tid, sb, m0, n0);

        const uint32_t sS = sb + (uint32_t)(t & (STAGES - 1)) * STAGE_SZ;
        // prime ks=0 fragments
#pragma unroll
        for (int mt = 0; mt < 4; ++mt)
            LDSM4(&af[0][mt * 4], sS + aOff + (uint32_t)mt * 2048 + swz[0]);
#pragma unroll
        for (int nh = 0; nh < 4; ++nh)
            LDSM4(&bf[0][nh * 4], sS + bOff + (uint32_t)nh * 2048 + swz[0]);

#pragma unroll
        for (int ks = 0; ks < 4; ++ks) {
            const int cb = ks & 1, nb = cb ^ 1;
            if (ks < 3) {   // prefetch next ks fragments (hidden behind MMAs)
#pragma unroll
                for (int mt = 0; mt < 4; ++mt)
                    LDSM4(&af[nb][mt * 4], sS + aOff + (uint32_t)mt * 2048 + swz[ks + 1]);
#pragma unroll
                for (int nh = 0; nh < 4; ++nh)
                    LDSM4(&bf[nb][nh * 4], sS + bOff + (uint32_t)nh * 2048 + swz[ks + 1]);
            }
#pragma unroll
            for (int mt = 0; mt < 4; ++mt)
#pragma unroll
                for (int nt = 0; nt < 8; ++nt)
                    mma16816(c[mt][nt], &af[cb][mt * 4],
                             bf[cb][(nt >> 1) * 4 + (nt & 1)],
                             bf[cb][(nt >> 1) * 4 + (nt & 1) + 2]);
        }
    }

    // ---- shuffle-based boosted winner-take-all + output ----
    // value c[mt][nt][rh*2+b] sits at row mt*16+rh*8+(lane>>2), col nt*8+(lane&3)*2+b
    const int g = lane >> 2, q = lane & 3;
#pragma unroll
    for (int mt = 0; mt < 4; ++mt) {
#pragma unroll
        for (int rh = 0; rh < 2; ++rh) {
            const int m = m0 + wm * 64 + mt * 16 + rh * 8 + g;
#pragma unroll
            for (int cc = 0; cc < 4; ++cc) {
                float bmax = -INFINITY, bsec = -INFINITY, dja = 0.0f;
                int ja = 0;
#pragma unroll
                for (int ntb = 0; ntb < 2; ++ntb) {
#pragma unroll
                    for (int b = 0; b < 2; ++b) {
                        const int j    = ntb * 8 + q * 2 + b;       // ascending order
                        const int colt = wn * 64 + cc * 16 + j;
                        float d  = c[mt][2 * cc + ntb][rh * 2 + b] + b1s_s[colt];
                        float bb = d * boost_s[colt];
                        if (bb > bmax) { bsec = bmax; bmax = bb; ja = j; dja = d; }
                        else if (bb > bsec) { bsec = bb; }
                    }
                }
#pragma unroll
                for (int off = 1; off <= 2; off <<= 1) {
                    float obmax = __shfl_xor_sync(0xffffffffu, bmax, off);
                    float obsec = __shfl_xor_sync(0xffffffffu, bsec, off);
                    float od    = __shfl_xor_sync(0xffffffffu, dja,  off);
                    int   oj    = __shfl_xor_sync(0xffffffffu, ja,   off);
                    if (obmax > bmax || (obmax == bmax && oj < ja)) {
                        bsec = fmaxf(bmax, obsec);
                        bmax = obmax; dja = od; ja = oj;
                    } else {
                        bsec = fmaxf(bsec, obmax);
                    }
                }
                if (q == 0) {
                    const int o = ntile * (TILE_N / DPC) + wn * 4 + cc;
                    out[(size_t)m * OUT_DIM + o] =
                        (dja * (1.0f / WSCALE)) * w2_s[wn * 64 + cc * 16 + ja] +
                        b2_s[wn * 4 + cc];
                    if (bmax - bsec < TAU) {
                        int idx = atomicAdd(&g_nflag, 1);
                        if (idx < FLAG_CAP) g_flags[idx] = (m << 10) | o;
                    }
                }
            }
        }
    }
}

// ---------------- bit-exact fixup for near-tie cells ----------------
// Reference dend is an ascending-k fp32 FMA chain; reproduce exactly:
// one lane per dendrite, sequential fmaf over k, + b1, * boost,
// 16-wide first-index argmax, fmaf output.
__global__ void fixup_kernel(const float* __restrict__ x,  const float* __restrict__ w1,
                             const float* __restrict__ b1, const float* __restrict__ w2,
                             const float* __restrict__ b2, float* __restrict__ out) {
    int n = g_nflag;
    if (n > FLAG_CAP) n = FLAG_CAP;
    const int gtid = blockIdx.x * blockDim.x + threadIdx.x;
    const int grp  = gtid >> 4;
    const int j    = gtid & 15;
    const int ngrp = (gridDim.x * blockDim.x) >> 4;
    for (int i = grp; i < n; i += ngrp) {
        const int f = g_flags[i];
        const int m = f >> 10, o = f & (OUT_DIM - 1);
        const float* xr = x  + (size_t)m * IN_DIM;
        const float* wr = w1 + (size_t)(o * DPC + j) * IN_DIM;
        float s = 0.0f;
#pragma unroll 8
        for (int k = 0; k < IN_DIM; ++k) s = fmaf(xr[k], wr[k], s);  // order preserved
        float d  = s + b1[o * DPC + j];
        float bb = d * g_boost[o * DPC + j];
        float bbb = bb, bd = d;
        int   bj  = j;
#pragma unroll
        for (int off = 8; off; off >>= 1) {
            float obb = __shfl_xor_sync(0xffffffffu, bbb, off);
            float od  = __shfl_xor_sync(0xffffffffu, bd,  off);
            int   oj  = __shfl_xor_sync(0xffffffffu, bj,  off);
            if (obb > bbb || (obb == bbb && oj < bj)) { bbb = obb; bd = od; bj = oj; }
        }
        if (j == 0) out[(size_t)m * OUT_DIM + o] = fmaf(bd, w2[o * DPC + bj], b2[o]);
    }
}

extern "C" void kernel_launch(void* const* d_in, const int* in_sizes, int n_in,
                              void* d_out, int out_size) {
    const float* x    = (const float*)d_in[0];
    const float* w1   = (const float*)d_in[1];
    const float* b1   = (const float*)d_in[2];
    const float* duty = (const float*)d_in[3];
    const float* w2   = (const float*)d_in[4];
    const float* b2   = (const float*)d_in[5];
    float* out = (float*)d_out;

    cudaFuncSetAttribute(gemm_kernel, cudaFuncAttributeMaxDynamicSharedMemorySize,
                         SMEM_BYTES);

    prep_misc_kernel<<<N_DEND / 256, 256>>>(duty, b1);
    split_x_kernel<<<(BATCH * IN_DIM) / 256, 256>>>(x);
    split_w_kernel<<<N_DEND * (IN_DIM / 256), 256>>>(w1);

    dim3 grid(N_DEND / TILE_N, BATCH / TILE_M);
    gemm_kernel<<<grid, THREADS, SMEM_BYTES>>>(w2, b2, out);
    fixup_kernel<<<512, 256>>>(x, w1, b1, w2, b2, out);
}

// round 8
// speedup vs baseline: 2.3467x; 1.0838x over previous
#include <cuda_runtime.h>
#include <cuda_fp16.h>
#include <math.h>
#include <stdint.h>

#define BATCH   4096
#define IN_DIM  1024
#define OUT_DIM 1024
#define DPC     16
#define N_DEND  16384

#define TILE_M  128
#define TILE_N  128
#define BK      64            // fp16 k per stage chunk (128B rows)
#define NCHUNK  48            // 3 passes * 1024 / 64
#define THREADS 256
#define STAGES  3
#define STAGE_SZ 32768        // A 16KB + B 16KB
#define B_OFF    16384
#define OFF_META (STAGES * STAGE_SZ)      // 98304
#define SMEM_BYTES (OFF_META + 2048)      // 100352 -> 2 CTAs/SM
#define WSCALE  1024.0f
#define TAU     0.01f
#define FLAG_CAP 65536

// ---------------- static device scratch ----------------
__device__ __align__(256) __half g_xh[BATCH * IN_DIM];
__device__ __align__(256) __half g_xl[BATCH * IN_DIM];
__device__ __align__(256) __half g_wh[(size_t)N_DEND * IN_DIM];
__device__ __align__(256) __half g_wl[(size_t)N_DEND * IN_DIM];
__device__ float g_boost[N_DEND];
__device__ float g_b1s[N_DEND];
__device__ int   g_flags[FLAG_CAP];
__device__ int   g_nflag;

// ---------------- PTX helpers (portable to compute_103) ----------------
__device__ __forceinline__ uint32_t smem_u32(const void* p) {
    uint32_t a;
    asm("{ .reg .u64 t; cvta.to.shared.u64 t, %1; cvt.u32.u64 %0, t; }" : "=r"(a) : "l"(p));
    return a;
}
__device__ __forceinline__ void cp16(uint32_t dst, const void* src) {
    asm volatile("cp.async.cg.shared.global [%0], [%1], 16;" :: "r"(dst), "l"(src) : "memory");
}
#define CP_COMMIT() asm volatile("cp.async.commit_group;" ::: "memory")

#define LDSM4(r, addr) \
    asm volatile("ldmatrix.sync.aligned.m8n8.x4.shared.b16 {%0,%1,%2,%3}, [%4];" \
                 : "=r"((r)[0]), "=r"((r)[1]), "=r"((r)[2]), "=r"((r)[3]) : "r"(addr))

__device__ __forceinline__ void mma16816(float* c, const uint32_t* a,
                                         uint32_t b0, uint32_t b1) {
    asm volatile(
        "mma.sync.aligned.m16n8k16.row.col.f32.f16.f16.f32 "
        "{%0,%1,%2,%3}, {%4,%5,%6,%7}, {%8,%9}, {%0,%1,%2,%3};"
        : "+f"(c[0]), "+f"(c[1]), "+f"(c[2]), "+f"(c[3])
        : "r"(a[0]), "r"(a[1]), "r"(a[2]), "r"(a[3]), "r"(b0), "r"(b1));
}

// ---------------- prep kernels ----------------
__global__ void prep_misc_kernel(const float* __restrict__ duty, const float* __restrict__ b1) {
    int i = blockIdx.x * blockDim.x + threadIdx.x;
    if (i < N_DEND) {
        g_boost[i] = expf((1.0f / DPC - duty[i]) * 2.0f);
        g_b1s[i]   = b1[i] * WSCALE;
    }
    if (i == 0) g_nflag = 0;
}
__global__ void split_x_kernel(const float* __restrict__ x) {
    int i = blockIdx.x * blockDim.x + threadIdx.x;
    if (i < BATCH * IN_DIM) {
        float v = x[i];
        __half h = __float2half_rn(v);
        g_xh[i] = h;
        g_xl[i] = __float2half_rn(v - __half2float(h));
    }
}
__global__ void split_w_kernel(const float* __restrict__ w1) {
    size_t i = (size_t)blockIdx.x * blockDim.x + threadIdx.x;
    if (i < (size_t)N_DEND * IN_DIM) {
        float v = w1[i] * WSCALE;
        __half h = __float2half_rn(v);
        g_wh[i] = h;
        g_wl[i] = __float2half_rn(v - __half2float(h));
    }
}

// ---------------- stage loader ----------------
__device__ __forceinline__ void load_chunk(int t, int tid, uint32_t sb, int m0, int n0) {
    const int pass = t >> 4;                  // 0: xh*wh, 1: xh*wl, 2: xl*wh
    const int kc   = (t & 15) * BK;
    const __half* Ab = (pass == 2) ? g_xl : g_xh;
    const __half* Bb = (pass == 1) ? g_wl : g_wh;
    const uint32_t sA = sb + (uint32_t)(t % STAGES) * STAGE_SZ;
    const uint32_t sB = sA + B_OFF;
#pragma unroll
    for (int i = 0; i < 4; ++i) {             // A: 128 rows x 8 chunks of 16B
        int e = tid + i * THREADS;
        int r = e >> 3, c = e & 7;
        cp16(sA + r * 128 + ((c ^ (r & 7)) << 4),
             Ab + (size_t)(m0 + r) * IN_DIM + kc + c * 8);
    }
#pragma unroll
    for (int i = 0; i < 4; ++i) {             // B: 128 rows x 8 chunks
        int e = tid + i * THREADS;
        int r = e >> 3, c = e & 7;
        cp16(sB + r * 128 + ((c ^ (r & 7)) << 4),
             Bb + (size_t)(n0 + r) * IN_DIM + kc + c * 8);
    }
    CP_COMMIT();
}

// ---------------- main fused GEMM + WTA epilogue ----------------
__global__ __launch_bounds__(THREADS, 2)
void gemm_kernel(const float* __restrict__ w2, const float* __restrict__ b2,
                 float* __restrict__ out) {
    extern __shared__ char smem[];
    const uint32_t sb = smem_u32(smem);
    const int tid  = threadIdx.x;
    const int wid  = tid >> 5, lane = tid & 31;
    const int wm   = wid & 1;              // warp m index (64-row block)
    const int wn   = wid >> 1;             // warp n index (32-col block)
    const int ntile = blockIdx.x, btile = blockIdx.y;
    const int m0 = btile * TILE_M, n0 = ntile * TILE_N;

    const int h    = lane >> 4;                        // k-half selector
    const int lr   = lane & 15;
    const uint32_t aOff = (uint32_t)(wm * 64 + lr) * 128;
    const uint32_t bOff = (uint32_t)(wn * 32 + lr) * 128 + B_OFF;
    uint32_t swz[4];
#pragma unroll
    for (int ks = 0; ks < 4; ++ks)
        swz[ks] = (uint32_t)(((ks * 2 + h) ^ (lr & 7)) << 4);

    float c[4][4][4];
#pragma unroll
    for (int i = 0; i < 4; ++i)
#pragma unroll
        for (int j = 0; j < 4; ++j)
#pragma unroll
            for (int k = 0; k < 4; ++k) c[i][j][k] = 0.0f;

    load_chunk(0, tid, sb, m0, n0);
    load_chunk(1, tid, sb, m0, n0);

    float* boost_s = (float*)(smem + OFF_META);
    float* b1s_s   = (float*)(smem + OFF_META + 512);
    float* w2_s    = (float*)(smem + OFF_META + 1024);
    float* b2_s    = (float*)(smem + OFF_META + 1536);
    if (tid < TILE_N) {
        boost_s[tid] = g_boost[n0 + tid];
        b1s_s[tid]   = g_b1s[n0 + tid];
        w2_s[tid]    = w2[n0 + tid];
    }
    if (tid < TILE_N / DPC) b2_s[tid] = b2[(n0 >> 4) + tid];

#pragma unroll 1
    for (int t = 0; t < NCHUNK; ++t) {
        if (t < NCHUNK - 1) asm volatile("cp.async.wait_group 1;" ::: "memory");
        else                asm volatile("cp.async.wait_group 0;" ::: "memory");
        __syncthreads();

        if (t + 2 < NCHUNK) load_chunk(t + 2, tid, sb, m0, n0);

        const uint32_t sS = sb + (uint32_t)(t % STAGES) * STAGE_SZ;
#pragma unroll
        for (int ks = 0; ks < 4; ++ks) {
            uint32_t af[16], bf[8];
#pragma unroll
            for (int mt = 0; mt < 4; ++mt)
                LDSM4(&af[mt * 4], sS + aOff + (uint32_t)mt * 2048 + swz[ks]);
#pragma unroll
            for (int nh = 0; nh < 2; ++nh)
                LDSM4(&bf[nh * 4], sS + bOff + (uint32_t)nh * 2048 + swz[ks]);
#pragma unroll
            for (int mt = 0; mt < 4; ++mt)
#pragma unroll
                for (int nt = 0; nt < 4; ++nt)
                    mma16816(c[mt][nt], &af[mt * 4],
                             bf[(nt >> 1) * 4 + (nt & 1)],
                             bf[(nt >> 1) * 4 + (nt & 1) + 2]);
        }
    }

    // ---- shuffle-based boosted winner-take-all + output ----
    // c[mt][nt][rh*2+b] at row mt*16+rh*8+(lane>>2), col nt*8+(lane&3)*2+b
    const int g = lane >> 2, q = lane & 3;
#pragma unroll
    for (int mt = 0; mt < 4; ++mt) {
#pragma unroll
        for (int rh = 0; rh < 2; ++rh) {
            const int m = m0 + wm * 64 + mt * 16 + rh * 8 + g;
#pragma unroll
            for (int cc = 0; cc < 2; ++cc) {
                float bmax = -INFINITY, bsec = -INFINITY, dja = 0.0f;
                int ja = 0;
#pragma unroll
                for (int ntb = 0; ntb < 2; ++ntb) {
#pragma unroll
                    for (int b = 0; b < 2; ++b) {
                        const int j    = ntb * 8 + q * 2 + b;       // ascending j
                        const int colt = wn * 32 + cc * 16 + j;
                        float d  = c[mt][2 * cc + ntb][rh * 2 + b] + b1s_s[colt];
                        float bb = d * boost_s[colt];
                        if (bb > bmax) { bsec = bmax; bmax = bb; ja = j; dja = d; }
                        else if (bb > bsec) { bsec = bb; }
                    }
                }
#pragma unroll
                for (int off = 1; off <= 2; off <<= 1) {
                    float obmax = __shfl_xor_sync(0xffffffffu, bmax, off);
                    float obsec = __shfl_xor_sync(0xffffffffu, bsec, off);
                    float od    = __shfl_xor_sync(0xffffffffu, dja,  off);
                    int   oj    = __shfl_xor_sync(0xffffffffu, ja,   off);
                    if (obmax > bmax || (obmax == bmax && oj < ja)) {
                        bsec = fmaxf(bmax, obsec);
                        bmax = obmax; dja = od; ja = oj;
                    } else {
                        bsec = fmaxf(bsec, obmax);
                    }
                }
                if (q == 0) {
                    const int o = ntile * (TILE_N / DPC) + wn * 2 + cc;
                    out[(size_t)m * OUT_DIM + o] =
                        (dja * (1.0f / WSCALE)) * w2_s[wn * 32 + cc * 16 + ja] +
                        b2_s[wn * 2 + cc];
                    if (bmax - bsec < TAU) {
                        int idx = atomicAdd(&g_nflag, 1);
                        if (idx < FLAG_CAP) g_flags[idx] = (m << 10) | o;
                    }
                }
            }
        }
    }
}

// ---------------- bit-exact fixup for near-tie cells ----------------
__global__ void fixup_kernel(const float* __restrict__ x,  const float* __restrict__ w1,
                             const float* __restrict__ b1, const float* __restrict__ w2,
                             const float* __restrict__ b2, float* __restrict__ out) {
    int n = g_nflag;
    if (n > FLAG_CAP) n = FLAG_CAP;
    const int gtid = blockIdx.x * blockDim.x + threadIdx.x;
    const int grp  = gtid >> 4;
    const int j    = gtid & 15;
    const int ngrp = (gridDim.x * blockDim.x) >> 4;
    for (int i = grp; i < n; i += ngrp) {
        const int f = g_flags[i];
        const int m = f >> 10, o = f & (OUT_DIM - 1);
        const float* xr = x  + (size_t)m * IN_DIM;
        const float* wr = w1 + (size_t)(o * DPC + j) * IN_DIM;
        float s = 0.0f;
#pragma unroll 8
        for (int k = 0; k < IN_DIM; ++k) s = fmaf(xr[k], wr[k], s);  // order preserved
        float d  = s + b1[o * DPC + j];
        float bb = d * g_boost[o * DPC + j];
        float bbb = bb, bd = d;
        int   bj  = j;
#pragma unroll
        for (int off = 8; off; off >>= 1) {
            float obb = __shfl_xor_sync(0xffffffffu, bbb, off);
            float od  = __shfl_xor_sync(0xffffffffu, bd,  off);
            int   oj  = __shfl_xor_sync(0xffffffffu, bj,  off);
            if (obb > bbb || (obb == bbb && oj < bj)) { bbb = obb; bd = od; bj = oj; }
        }
        if (j == 0) out[(size_t)m * OUT_DIM + o] = fmaf(bd, w2[o * DPC + bj], b2[o]);
    }
}

extern "C" void kernel_launch(void* const* d_in, const int* in_sizes, int n_in,
                              void* d_out, int out_size) {
    const float* x    = (const float*)d_in[0];
    const float* w1   = (const float*)d_in[1];
    const float* b1   = (const float*)d_in[2];
    const float* duty = (const float*)d_in[3];
    const float* w2   = (const float*)d_in[4];
    const float* b2   = (const float*)d_in[5];
    float* out = (float*)d_out;

    cudaFuncSetAttribute(gemm_kernel, cudaFuncAttributeMaxDynamicSharedMemorySize,
                         SMEM_BYTES);

    prep_misc_kernel<<<N_DEND / 256, 256>>>(duty, b1);
    split_x_kernel<<<(BATCH * IN_DIM) / 256, 256>>>(x);
    split_w_kernel<<<N_DEND * (IN_DIM / 256), 256>>>(w1);

    dim3 grid(N_DEND / TILE_N, BATCH / TILE_M);
    gemm_kernel<<<grid, THREADS, SMEM_BYTES>>>(w2, b2, out);
    fixup_kernel<<<512, 256>>>(x, w1, b1, w2, b2, out);
}